// round 5
// baseline (speedup 1.0000x reference)
#include <cuda_runtime.h>
#include <cstdint>
#include <math.h>

// Problem constants
#define BDIM   4
#define TDIM   4096
#define DDIM   2048
#define DBDIM  512
#define BT     (BDIM * TDIM)   // 16384 tokens
#define EPSV   1e-6f

// ---------------- scratch (static device globals; no runtime allocation) ----
__device__ float g_z  [(size_t)BT * DBDIM];        //  33.5 MB  bottleneck proj
__device__ float g_zm [(size_t)BT * 3 * DBDIM];    // 100.7 MB  z @ [M0|M1|M2]
__device__ float g_y  [(size_t)BT * DBDIM];        //  33.5 MB  mixed
__device__ float g_k  [(size_t)BT * DDIM];         // 134.2 MB  key proj
__device__ float g_v  [(size_t)BT * DDIM];         // 134.2 MB  value proj
__device__ float g_n  [(size_t)BT * DDIM];         // 134.2 MB  rms(gated out)
__device__ float g_wc [(size_t)3 * DBDIM * DBDIM]; //   3.1 MB  combined mix W [1536,512]

// ---------------------------------------------------------------------------
// helpers
// ---------------------------------------------------------------------------
__device__ __forceinline__ uint32_t s2u(const void* p) {
    uint32_t a;
    asm("{ .reg .u64 t; cvta.to.shared.u64 t, %1; cvt.u32.u64 %0, t; }"
        : "=r"(a) : "l"(p));
    return a;
}

__device__ __forceinline__ void cp16(uint32_t dst, const void* src) {
    asm volatile("cp.async.cg.shared.global [%0], [%1], 16;" :: "r"(dst), "l"(src));
}
__device__ __forceinline__ void cp_commit() {
    asm volatile("cp.async.commit_group;" ::: "memory");
}
template<int N> __device__ __forceinline__ void cp_wait() {
    asm volatile("cp.async.wait_group %0;" :: "n"(N) : "memory");
}

// shared load + round-to-nearest tf32 (dest .b32 per PTX spec)
__device__ __forceinline__ uint32_t lds_tf32(uint32_t addr) {
    uint32_t v, r;
    asm volatile("ld.shared.b32 %0, [%1];" : "=r"(v) : "r"(addr));
    asm("cvt.rna.tf32.f32 %0, %1;" : "=r"(r) : "f"(__uint_as_float(v)));
    return r;
}

// mma.sync m16n8k8 tf32 (legacy tensor path, valid on compute_100)
__device__ __forceinline__ void mma_tf32(float& c0, float& c1, float& c2, float& c3,
                                         uint32_t a0, uint32_t a1, uint32_t a2,
                                         uint32_t a3, uint32_t b0, uint32_t b1) {
    asm volatile(
        "mma.sync.aligned.m16n8k8.row.col.f32.tf32.tf32.f32 "
        "{%0,%1,%2,%3}, {%4,%5,%6,%7}, {%8,%9}, {%0,%1,%2,%3};"
        : "+f"(c0), "+f"(c1), "+f"(c2), "+f"(c3)
        : "r"(a0), "r"(a1), "r"(a2), "r"(a3), "r"(b0), "r"(b1));
}

// ---------------------------------------------------------------------------
// TF32 tensor-core NT GEMM: C[M,N] = A[M,K] * W[N,K]^T, fp32 accumulate.
// Raw fp32 operands; tf32 RNA rounding fused into fragment loads.
// 128x128x32 block tile, 8 warps (4m x 2n), warp tile 32x64, 2-stage cp.async,
// 2 CTAs/SM. SMEM rows padded to 36 floats -> conflict-free fragment loads.
// Optional second W/C (blockIdx.z selects) to fuse k/v projections.
// ---------------------------------------------------------------------------
#define TBM    128
#define TBN    128
#define TBK    32
#define NSTG   2
#define LROW   36                       // padded row stride (floats)
#define STG_B  (128 * LROW * 4)         // 18432 bytes per operand per stage
#define SOFF_B (NSTG * STG_B)
#define GEMM_SMEM (2 * NSTG * STG_B)    // 73728 bytes

__global__ void __launch_bounds__(256, 2)
gemm_tc(const float* __restrict__ A,
        const float* __restrict__ W0, const float* __restrict__ W1,
        float* __restrict__ C0, float* __restrict__ C1,
        int N, int K) {
    extern __shared__ __align__(16) char smem[];
    const uint32_t sb = s2u(smem);

    const float* __restrict__ W = (blockIdx.z == 0) ? W0 : W1;
    float* __restrict__ C = (blockIdx.z == 0) ? C0 : C1;

    const int tid  = threadIdx.x;
    const int lane = tid & 31;
    const int wid  = tid >> 5;
    const int wm   = (wid & 3) * 32;      // warp row offset in tile
    const int wn   = (wid >> 2) * 64;     // warp col offset in tile
    const int g    = lane >> 2;           // groupID 0..7
    const int tg   = lane & 3;            // thread-in-group 0..3

    const int bm = blockIdx.y * TBM;
    const int bn = blockIdx.x * TBN;
    const int num_k = K / TBK;

    const float* Abase = A + (size_t)bm * K;
    const float* Wbase = W + (size_t)bn * K;

    auto load_stage = [&](int ks, int buf) {
        const float* Ap = Abase + ks * TBK;
        const float* Wp = Wbase + ks * TBK;
        uint32_t ab = sb + buf * STG_B;
        uint32_t bb = sb + SOFF_B + buf * STG_B;
        #pragma unroll
        for (int i = 0; i < 4; i++) {             // 1024 16B chunks / 256 thr
            int idx = tid + i * 256;
            int r = idx >> 3, c4 = idx & 7;
            cp16(ab + r * (LROW * 4) + c4 * 16, Ap + (size_t)r * K + c4 * 4);
        }
        #pragma unroll
        for (int i = 0; i < 4; i++) {
            int idx = tid + i * 256;
            int r = idx >> 3, c4 = idx & 7;
            cp16(bb + r * (LROW * 4) + c4 * 16, Wp + (size_t)r * K + c4 * 4);
        }
        cp_commit();
    };

    float acc[2][8][4];
    #pragma unroll
    for (int mi = 0; mi < 2; mi++)
        #pragma unroll
        for (int ni = 0; ni < 8; ni++)
            #pragma unroll
            for (int c = 0; c < 4; c++) acc[mi][ni][c] = 0.f;

    load_stage(0, 0);

    for (int k = 0; k < num_k; k++) {
        int buf = k & 1;
        if (k + 1 < num_k) load_stage(k + 1, buf ^ 1); else cp_commit();
        cp_wait<1>();                    // stage k resident
        __syncthreads();

        uint32_t ab = sb + buf * STG_B;
        uint32_t bb = sb + SOFF_B + buf * STG_B;

        #pragma unroll
        for (int ks = 0; ks < 4; ks++) {         // 4 x k8 slices
            const int kk = ks * 8;
            uint32_t af[2][4], bf[8][2];
            #pragma unroll
            for (int mi = 0; mi < 2; mi++) {
                int r0 = wm + mi * 16 + g;
                uint32_t base0 = ab + (r0)     * (LROW * 4) + (kk + tg) * 4;
                uint32_t base1 = ab + (r0 + 8) * (LROW * 4) + (kk + tg) * 4;
                af[mi][0] = lds_tf32(base0);
                af[mi][1] = lds_tf32(base1);
                af[mi][2] = lds_tf32(base0 + 16);
                af[mi][3] = lds_tf32(base1 + 16);
            }
            #pragma unroll
            for (int ni = 0; ni < 8; ni++) {
                int n0 = wn + ni * 8 + g;
                uint32_t base = bb + n0 * (LROW * 4) + (kk + tg) * 4;
                bf[ni][0] = lds_tf32(base);
                bf[ni][1] = lds_tf32(base + 16);
            }
            #pragma unroll
            for (int mi = 0; mi < 2; mi++)
                #pragma unroll
                for (int ni = 0; ni < 8; ni++)
                    mma_tf32(acc[mi][ni][0], acc[mi][ni][1],
                             acc[mi][ni][2], acc[mi][ni][3],
                             af[mi][0], af[mi][1], af[mi][2], af[mi][3],
                             bf[ni][0], bf[ni][1]);
        }
        __syncthreads();                 // readers done before next refill
    }

    // epilogue: direct float2 stores
    #pragma unroll
    for (int mi = 0; mi < 2; mi++) {
        #pragma unroll
        for (int ni = 0; ni < 8; ni++) {
            int row = bm + wm + mi * 16 + g;
            int col = bn + wn + ni * 8 + tg * 2;
            *(float2*)(C + (size_t)row * N + col) =
                make_float2(acc[mi][ni][0], acc[mi][ni][1]);
            *(float2*)(C + (size_t)(row + 8) * N + col) =
                make_float2(acc[mi][ni][2], acc[mi][ni][3]);
        }
    }
}

// ---------------------------------------------------------------------------
// Combine W_mix[3,512,512] into wc[1536,512] row-major (N=1536 rows, K=512):
//   rows [0,512)    = M0 = W2/6 + W3/9 + W4/12   (shifts 0,1)
//   rows [512,1024) = M1 = W3/9 + W4/12          (shift 2)
//   rows [1024,1536)= M2 = W4/12                 (shift 3)
// ---------------------------------------------------------------------------
__global__ void combine_wmix(const float* __restrict__ wmix, float* __restrict__ wc) {
    int idx = blockIdx.x * blockDim.x + threadIdx.x;      // f*512 + e
    if (idx >= DBDIM * DBDIM) return;
    float w2 = wmix[0 * DBDIM * DBDIM + idx];
    float w3 = wmix[1 * DBDIM * DBDIM + idx];
    float w4 = wmix[2 * DBDIM * DBDIM + idx];
    const float c2 = 1.0f / 6.0f, c3 = 1.0f / 9.0f, c4 = 1.0f / 12.0f;
    wc[idx]                         = w2 * c2 + w3 * c3 + w4 * c4;
    wc[DBDIM * DBDIM + idx]         = w3 * c3 + w4 * c4;
    wc[2 * DBDIM * DBDIM + idx]     = w4 * c4;
}

// ---------------------------------------------------------------------------
// Gather y[t] = zm0[t] + m1*zm0[t-1] + m2*zm1[t-2] + m3*zm2[t-3]
// zm row layout: [blk0 | blk1 | blk2], 512 floats each.
// ---------------------------------------------------------------------------
__global__ void __launch_bounds__(128)
build_y(const float* __restrict__ zm, const int* __restrict__ doc,
        float* __restrict__ y) {
    int t  = blockIdx.x;
    int tt = t & (TDIM - 1);
    int d0 = doc[t];
    bool m1 = (tt >= 1) && (doc[t - 1] == d0);
    bool m2 = (tt >= 2) && (doc[t - 2] == d0);
    bool m3 = (tt >= 3) && (doc[t - 3] == d0);

    const float4* p0 = (const float4*)(zm + (size_t)t * 1536);             // blk0
    const float4* p1 = (const float4*)(zm + (size_t)(t - 1) * 1536);       // blk0
    const float4* p2 = (const float4*)(zm + (size_t)(t - 2) * 1536 + 512); // blk1
    const float4* p3 = (const float4*)(zm + (size_t)(t - 3) * 1536 + 1024);// blk2

    int i = threadIdx.x;                 // 128 float4 = 512 floats
    float4 a = p0[i];
    if (m1) { float4 b = p1[i]; a.x += b.x; a.y += b.y; a.z += b.z; a.w += b.w; }
    if (m2) { float4 b = p2[i]; a.x += b.x; a.y += b.y; a.z += b.z; a.w += b.w; }
    if (m3) { float4 b = p3[i]; a.x += b.x; a.y += b.y; a.z += b.z; a.w += b.w; }
    ((float4*)(y + (size_t)t * DBDIM))[i] = a;
}

// ---------------------------------------------------------------------------
// Gate + rms(out)
// ---------------------------------------------------------------------------
__global__ void __launch_bounds__(256)
gate_norm(const float* __restrict__ x, const float* __restrict__ k,
          const float* __restrict__ v, float* __restrict__ nrm) {
    int t = blockIdx.x;
    const float4* xp = (const float4*)(x + (size_t)t * DDIM);
    const float4* kp = (const float4*)(k + (size_t)t * DDIM);
    const float4* vp = (const float4*)(v + (size_t)t * DDIM);

    float sxx = 0.f, sxk = 0.f, skk = 0.f, svv = 0.f;
    float4 vreg[2];
    #pragma unroll
    for (int r = 0; r < 2; r++) {
        int i = threadIdx.x + r * 256;
        float4 xa = xp[i], ka = kp[i], va = vp[i];
        vreg[r] = va;
        sxx += xa.x * xa.x + xa.y * xa.y + xa.z * xa.z + xa.w * xa.w;
        sxk += xa.x * ka.x + xa.y * ka.y + xa.z * ka.z + xa.w * ka.w;
        skk += ka.x * ka.x + ka.y * ka.y + ka.z * ka.z + ka.w * ka.w;
        svv += va.x * va.x + va.y * va.y + va.z * va.z + va.w * va.w;
    }
    #pragma unroll
    for (int off = 16; off > 0; off >>= 1) {
        sxx += __shfl_down_sync(0xffffffffu, sxx, off);
        sxk += __shfl_down_sync(0xffffffffu, sxk, off);
        skk += __shfl_down_sync(0xffffffffu, skk, off);
        svv += __shfl_down_sync(0xffffffffu, svv, off);
    }
    __shared__ float sh[4][8];
    __shared__ float s_scale;
    int warp = threadIdx.x >> 5, lane = threadIdx.x & 31;
    if (lane == 0) {
        sh[0][warp] = sxx; sh[1][warp] = sxk; sh[2][warp] = skk; sh[3][warp] = svv;
    }
    __syncthreads();
    if (threadIdx.x == 0) {
        float a0 = 0.f, a1 = 0.f, a2 = 0.f, a3 = 0.f;
        #pragma unroll
        for (int w = 0; w < 8; w++) {
            a0 += sh[0][w]; a1 += sh[1][w]; a2 += sh[2][w]; a3 += sh[3][w];
        }
        const float invD = 1.0f / (float)DDIM;
        float g = a1 * rsqrtf(a0 * invD + EPSV) * rsqrtf(a2 * invD + EPSV)
                     * rsqrtf((float)DDIM);
        float sg = (g > 0.f) ? 1.f : ((g < 0.f) ? -1.f : 0.f);
        float gl = sg * sqrtf(fmaxf(fabsf(g), 1e-6f));
        float gate = 1.0f / (1.0f + expf(-gl));
        float mv = a3 * invD;
        s_scale = gate * rsqrtf(gate * gate * mv + EPSV);
    }
    __syncthreads();
    float sc = s_scale;
    float4* np = (float4*)(nrm + (size_t)t * DDIM);
    #pragma unroll
    for (int r = 0; r < 2; r++) {
        int i = threadIdx.x + r * 256;
        float4 va = vreg[r];
        va.x *= sc; va.y *= sc; va.z *= sc; va.w *= sc;
        np[i] = va;
    }
}

// ---------------------------------------------------------------------------
// Depthwise causal conv (K=4) + SiLU
// ---------------------------------------------------------------------------
__global__ void __launch_bounds__(256)
conv_silu(const float* __restrict__ nrm, const int* __restrict__ doc,
          const float* __restrict__ cw, float* __restrict__ out) {
    int t  = blockIdx.x;
    int tt = t & (TDIM - 1);
    int d0 = doc[t];
    bool m1 = (tt >= 1) && (doc[t - 1] == d0);
    bool m2 = (tt >= 2) && (doc[t - 2] == d0);
    bool m3 = (tt >= 3) && (doc[t - 3] == d0);

    const float* n0 = nrm + (size_t)t * DDIM;
    const float* n1 = nrm + (size_t)(t - 1) * DDIM;
    const float* n2 = nrm + (size_t)(t - 2) * DDIM;
    const float* n3 = nrm + (size_t)(t - 3) * DDIM;
    float4 zero = make_float4(0.f, 0.f, 0.f, 0.f);

    #pragma unroll
    for (int r = 0; r < 2; r++) {
        int d4 = threadIdx.x + r * 256;
        int d  = d4 * 4;
        float4 a0 = *(const float4*)(n0 + d);
        float4 a1 = m1 ? *(const float4*)(n1 + d) : zero;
        float4 a2 = m2 ? *(const float4*)(n2 + d) : zero;
        float4 a3 = m3 ? *(const float4*)(n3 + d) : zero;

        const float* p0 = (const float*)&a0;
        const float* p1 = (const float*)&a1;
        const float* p2 = (const float*)&a2;
        const float* p3 = (const float*)&a3;

        float4 o;
        float* po = (float*)&o;
        #pragma unroll
        for (int i = 0; i < 4; i++) {
            float4 w = *(const float4*)(cw + (size_t)(d + i) * 4);
            float res = p0[i] * w.w + p1[i] * w.z + p2[i] * w.y + p3[i] * w.x;
            po[i] = res / (1.0f + expf(-res));
        }
        *(float4*)(out + (size_t)t * DDIM + d) = o;
    }
}

// ---------------------------------------------------------------------------
extern "C" void kernel_launch(void* const* d_in, const int* in_sizes, int n_in,
                              void* d_out, int out_size) {
    const float* x      = (const float*)d_in[0];
    const int*   doc    = (const int*)  d_in[1];
    const float* W_in   = (const float*)d_in[2];
    const float* W_mix  = (const float*)d_in[3];
    const float* W_k    = (const float*)d_in[4];
    const float* W_v    = (const float*)d_in[5];
    const float* conv_w = (const float*)d_in[6];
    float* out = (float*)d_out;

    float *z, *zm, *y, *k, *v, *n, *wc;
    cudaGetSymbolAddress((void**)&z,  g_z);
    cudaGetSymbolAddress((void**)&zm, g_zm);
    cudaGetSymbolAddress((void**)&y,  g_y);
    cudaGetSymbolAddress((void**)&k,  g_k);
    cudaGetSymbolAddress((void**)&v,  g_v);
    cudaGetSymbolAddress((void**)&n,  g_n);
    cudaGetSymbolAddress((void**)&wc, g_wc);

    cudaFuncSetAttribute(gemm_tc,
                         cudaFuncAttributeMaxDynamicSharedMemorySize, GEMM_SMEM);

    // 1) combined mix weights wc[1536,512]
    combine_wmix<<<(DBDIM * DBDIM + 255) / 256, 256>>>(W_mix, wc);

    // 2) z = x @ W_in^T : [16384,2048] x [512,2048]^T
    gemm_tc<<<dim3(DBDIM / TBN, BT / TBM, 1), 256, GEMM_SMEM>>>(
        x, W_in, W_in, z, z, DBDIM, DDIM);

    // 3) zm = z @ wc^T : [16384,512] x [1536,512]^T
    gemm_tc<<<dim3(3 * DBDIM / TBN, BT / TBM, 1), 256, GEMM_SMEM>>>(
        z, wc, wc, zm, zm, 3 * DBDIM, DBDIM);

    // 4) y gather from shifted zm blocks
    build_y<<<BT, 128>>>(zm, doc, y);

    // 5) k = y @ W_k^T, v = y @ W_v^T (fused via blockIdx.z)
    gemm_tc<<<dim3(DDIM / TBN, BT / TBM, 2), 256, GEMM_SMEM>>>(
        y, W_k, W_v, k, v, DDIM, DBDIM);

    // 6) gate + rms-norm of gated output
    gate_norm<<<BT, 256>>>(x, k, v, n);

    // 7) depthwise causal conv + SiLU -> final output
    conv_silu<<<BT, 256>>>(n, doc, conv_w, out);
}